// round 3
// baseline (speedup 1.0000x reference)
#include <cuda_runtime.h>
#include <cuda_bf16.h>
#include <math.h>

// ---------------------------------------------------------------------------
// GAT 2-layer pipeline.
// Sizes (fixed by the problem): N=50000, E=800000 (+N self loops),
// F_IN=128, L1: heads=4, hid=32 (HT1=128), L2: heads=1, out=64 (HT2=64).
// edge_index dtype is detected at runtime (int32 vs int64) since JAX's
// default config downcasts int64 -> int32.
// ---------------------------------------------------------------------------

#define NMAX     50000
#define EMAX     800000
#define ETOTMAX  (EMAX + NMAX)

// scratch (device globals; no cudaMalloc allowed). 16B-aligned for float4/red.v4.
__device__ __align__(16) float g_H1[NMAX * 128];
__device__ __align__(16) float g_as1[NMAX * 4];
__device__ __align__(16) float g_ad1[NMAX * 4];
__device__ __align__(16) int   g_emax1[NMAX * 4];
__device__ __align__(16) float g_denom1[NMAX * 4];
__device__ __align__(16) float g_eexp1[ETOTMAX * 4];
__device__ __align__(16) float g_out1[NMAX * 128];
__device__ __align__(16) float g_H2[NMAX * 64];
__device__ __align__(16) float g_as2[NMAX];
__device__ __align__(16) float g_ad2[NMAX];
__device__ __align__(16) int   g_emax2[NMAX];
__device__ __align__(16) float g_denom2[NMAX];
__device__ __align__(16) float g_eexp2[ETOTMAX];
__device__ int g_is64;   // 1 if edge_index is int64, 0 if int32

// ---------------------------------------------------------------------------
// dtype detect: if edge_index is little-endian int64 with values < 2^31,
// every odd int32 word is 0. For int32 data the odd words are random node ids.
// ---------------------------------------------------------------------------
__global__ void detect_dtype_kernel(const int* __restrict__ ei32)
{
    int all_zero = 1;
    #pragma unroll
    for (int i = 1; i < 64; i += 2)
        if (ei32[i] != 0) all_zero = 0;
    g_is64 = all_zero;
}

// fetch src/dst for edge e (handles self loops appended at e >= E)
__device__ __forceinline__ void edge_sd(const int* __restrict__ ei32,
                                        long long e, int E, int is64,
                                        int& s, int& d)
{
    if (e < E) {
        if (is64) { s = ei32[2 * e]; d = ei32[2 * ((long long)E + e)]; }
        else      { s = ei32[e];     d = ei32[(long long)E + e]; }
    } else {
        s = d = (int)(e - E);
    }
}

// ---------------------------------------------------------------------------
// GEMM: C[N, COLS] = A[N, 128] @ W[128, COLS], fp32 SIMT, W cached in L1.
// 256 threads, tile M=64, full K=128.
// ---------------------------------------------------------------------------
template <int COLS>
__global__ __launch_bounds__(256) void gemm_kernel(
    const float* __restrict__ A, const float* __restrict__ W,
    float* __restrict__ C, int N)
{
    constexpr int K = 128;
    constexpr int MTILE = 64;
    constexpr int G = COLS / 4;       // column groups (float4)
    constexpr int R = 256 / G;        // row groups
    constexpr int RT = MTILE / R;     // rows per thread

    __shared__ float Xs[MTILE][K];

    const int tid = threadIdx.x;
    const int block_row = blockIdx.x * MTILE;

    #pragma unroll
    for (int i = tid; i < MTILE * (K / 4); i += 256) {
        int r = i / (K / 4);
        int c4 = i % (K / 4);
        int gr = block_row + r;
        float4 v = make_float4(0.f, 0.f, 0.f, 0.f);
        if (gr < N) v = ((const float4*)A)[(size_t)gr * (K / 4) + c4];
        *(float4*)&Xs[r][c4 * 4] = v;
    }
    __syncthreads();

    const int cg = tid % G;
    const int rg = tid / G;

    float acc[RT][4];
    #pragma unroll
    for (int r = 0; r < RT; r++) {
        acc[r][0] = 0.f; acc[r][1] = 0.f; acc[r][2] = 0.f; acc[r][3] = 0.f;
    }

    #pragma unroll 4
    for (int k = 0; k < K; k++) {
        float4 w = ((const float4*)W)[k * G + cg];
        #pragma unroll
        for (int r = 0; r < RT; r++) {
            float a = Xs[rg * RT + r][k];
            acc[r][0] = fmaf(a, w.x, acc[r][0]);
            acc[r][1] = fmaf(a, w.y, acc[r][1]);
            acc[r][2] = fmaf(a, w.z, acc[r][2]);
            acc[r][3] = fmaf(a, w.w, acc[r][3]);
        }
    }

    #pragma unroll
    for (int r = 0; r < RT; r++) {
        int gr = block_row + rg * RT + r;
        if (gr < N)
            ((float4*)C)[(size_t)gr * G + cg] =
                make_float4(acc[r][0], acc[r][1], acc[r][2], acc[r][3]);
    }
}

// ---------------------------------------------------------------------------
// per-node attention coefficients: as[n,h] = sum_c H[n,h,c]*att_s[h,c]
// ---------------------------------------------------------------------------
template <int HT, int HEADS>
__global__ void asad_kernel(const float* __restrict__ H,
                            const float* __restrict__ att_s,
                            const float* __restrict__ att_d,
                            float* __restrict__ as_out,
                            float* __restrict__ ad_out)
{
    constexpr int C = HT / HEADS;
    constexpr int NWARPS = HT / 32;
    constexpr int WPH = C / 32;  // warps per head (1 or 2)

    const int n = blockIdx.x;
    const int t = threadIdx.x;

    float h = H[(size_t)n * HT + t];
    float ps = h * att_s[t];
    float pd = h * att_d[t];

    #pragma unroll
    for (int off = 16; off > 0; off >>= 1) {
        ps += __shfl_xor_sync(0xffffffffu, ps, off);
        pd += __shfl_xor_sync(0xffffffffu, pd, off);
    }

    __shared__ float ss[NWARPS], sd[NWARPS];
    if ((t & 31) == 0) { ss[t >> 5] = ps; sd[t >> 5] = pd; }
    __syncthreads();

    if (t < HEADS) {
        float s = 0.f, d = 0.f;
        #pragma unroll
        for (int w = 0; w < WPH; w++) {
            s += ss[t * WPH + w];
            d += sd[t * WPH + w];
        }
        as_out[n * HEADS + t] = s;
        ad_out[n * HEADS + t] = d;
    }
}

// ---------------------------------------------------------------------------
// init kernels
// ---------------------------------------------------------------------------
__global__ void init_out_kernel(float* __restrict__ out, const float* __restrict__ bias,
                                int total, int HT)
{
    int i = blockIdx.x * blockDim.x + threadIdx.x;
    if (i < total) out[i] = bias[i % HT];
}

__global__ void init_softmax_kernel(int* __restrict__ emax, float* __restrict__ denom, int total)
{
    int i = blockIdx.x * blockDim.x + threadIdx.x;
    if (i < total) { emax[i] = 0x80000000; denom[i] = 0.f; }
}

// monotone float<->int key
__device__ __forceinline__ int f2key(float f) {
    int i = __float_as_int(f);
    return i >= 0 ? i : (i ^ 0x7FFFFFFF);
}
__device__ __forceinline__ float key2f(int i) {
    return __int_as_float(i >= 0 ? i : (i ^ 0x7FFFFFFF));
}

// ---------------------------------------------------------------------------
// edge pass 1: segment max of leaky_relu(as[src]+ad[dst])
// ---------------------------------------------------------------------------
template <int HEADS>
__global__ void edge_max_kernel(const int* __restrict__ ei,
                                const float* __restrict__ as_,
                                const float* __restrict__ ad_,
                                int* __restrict__ emax, int E, int N)
{
    int idx = blockIdx.x * blockDim.x + threadIdx.x;
    int total = (E + N) * HEADS;
    if (idx >= total) return;
    int e = idx / HEADS;
    int h = idx - e * HEADS;
    int s, d;
    edge_sd(ei, e, E, g_is64, s, d);
    float v = as_[s * HEADS + h] + ad_[d * HEADS + h];
    v = v > 0.f ? v : 0.2f * v;
    atomicMax(&emax[d * HEADS + h], f2key(v));
}

// ---------------------------------------------------------------------------
// edge pass 2: e_exp = exp(v - max[dst]); denom[dst] += e_exp
// ---------------------------------------------------------------------------
template <int HEADS>
__global__ void edge_exp_kernel(const int* __restrict__ ei,
                                const float* __restrict__ as_,
                                const float* __restrict__ ad_,
                                const int* __restrict__ emax,
                                float* __restrict__ eexp,
                                float* __restrict__ denom, int E, int N)
{
    int idx = blockIdx.x * blockDim.x + threadIdx.x;
    int total = (E + N) * HEADS;
    if (idx >= total) return;
    int e = idx / HEADS;
    int h = idx - e * HEADS;
    int s, d;
    edge_sd(ei, e, E, g_is64, s, d);
    float v = as_[s * HEADS + h] + ad_[d * HEADS + h];
    v = v > 0.f ? v : 0.2f * v;
    float m = key2f(emax[d * HEADS + h]);
    float ex = __expf(v - m);
    eexp[e * HEADS + h] = ex;
    atomicAdd(&denom[d * HEADS + h], ex);
}

// ---------------------------------------------------------------------------
// edge pass 3: out[dst] += h[src] * alpha   (vector red.global.add)
// ---------------------------------------------------------------------------
template <int HT, int HEADS>
__global__ __launch_bounds__(256) void edge_aggregate_kernel(
    const int* __restrict__ ei,
    const float* __restrict__ H,
    const float* __restrict__ eexp,
    const float* __restrict__ denom,
    float* __restrict__ out, int E, int N)
{
    constexpr int LPE = HT / 4;      // lanes per edge
    constexpr int EPW = 32 / LPE;    // edges per warp
    constexpr int HID = HT / HEADS;

    int gtid = blockIdx.x * blockDim.x + threadIdx.x;
    int w = gtid >> 5;
    int lane = gtid & 31;
    int sub = lane / LPE;
    int le = lane - sub * LPE;

    long long e = (long long)w * EPW + sub;
    int etot = E + N;
    if (e >= etot) return;

    int s, d;
    edge_sd(ei, e, E, g_is64, s, d);

    int h = (le * 4) / HID;
    float alpha = eexp[e * HEADS + h] / denom[d * HEADS + h];

    float4 hv = ((const float4*)H)[(size_t)s * LPE + le];
    float4 m = make_float4(hv.x * alpha, hv.y * alpha, hv.z * alpha, hv.w * alpha);

    float* dst_ptr = out + (size_t)d * HT + le * 4;
    asm volatile("red.global.add.v4.f32 [%0], {%1, %2, %3, %4};"
                 :: "l"(dst_ptr), "f"(m.x), "f"(m.y), "f"(m.z), "f"(m.w)
                 : "memory");
}

// ---------------------------------------------------------------------------
// ELU in place
// ---------------------------------------------------------------------------
__global__ void elu_kernel(float* __restrict__ x, int total)
{
    int i = blockIdx.x * blockDim.x + threadIdx.x;
    if (i < total) {
        float v = x[i];
        x[i] = v > 0.f ? v : expm1f(v);
    }
}

// ---------------------------------------------------------------------------
// launch
// ---------------------------------------------------------------------------
extern "C" void kernel_launch(void* const* d_in, const int* in_sizes, int n_in,
                              void* d_out, int out_size)
{
    const float* x    = (const float*)d_in[0];
    const int*   ei   = (const int*)d_in[1];     // int32 or packed int64, detected
    const float* W1   = (const float*)d_in[2];
    const float* as1w = (const float*)d_in[3];
    const float* ad1w = (const float*)d_in[4];
    const float* b1   = (const float*)d_in[5];
    const float* W2   = (const float*)d_in[6];
    const float* as2w = (const float*)d_in[7];
    const float* ad2w = (const float*)d_in[8];
    const float* b2   = (const float*)d_in[9];
    float* out = (float*)d_out;

    const int N = in_sizes[0] / 128;   // 50000
    const int E = in_sizes[1] / 2;     // 800000 (element count = 2E for both dtypes)
    const int ETOT = E + N;

    float *H1, *as1, *ad1, *denom1, *eexp1, *out1;
    float *H2, *as2, *ad2, *denom2, *eexp2;
    int *emax1, *emax2;
    cudaGetSymbolAddress((void**)&H1, g_H1);
    cudaGetSymbolAddress((void**)&as1, g_as1);
    cudaGetSymbolAddress((void**)&ad1, g_ad1);
    cudaGetSymbolAddress((void**)&emax1, g_emax1);
    cudaGetSymbolAddress((void**)&denom1, g_denom1);
    cudaGetSymbolAddress((void**)&eexp1, g_eexp1);
    cudaGetSymbolAddress((void**)&out1, g_out1);
    cudaGetSymbolAddress((void**)&H2, g_H2);
    cudaGetSymbolAddress((void**)&as2, g_as2);
    cudaGetSymbolAddress((void**)&ad2, g_ad2);
    cudaGetSymbolAddress((void**)&emax2, g_emax2);
    cudaGetSymbolAddress((void**)&denom2, g_denom2);
    cudaGetSymbolAddress((void**)&eexp2, g_eexp2);

    detect_dtype_kernel<<<1, 1>>>(ei);

    // ---------- Layer 1 (HT=128, HEADS=4) ----------
    gemm_kernel<128><<<(N + 63) / 64, 256>>>(x, W1, H1, N);
    asad_kernel<128, 4><<<N, 128>>>(H1, as1w, ad1w, as1, ad1);
    init_out_kernel<<<(N * 128 + 255) / 256, 256>>>(out1, b1, N * 128, 128);
    init_softmax_kernel<<<(N * 4 + 255) / 256, 256>>>(emax1, denom1, N * 4);
    {
        int total = ETOT * 4;
        edge_max_kernel<4><<<(total + 255) / 256, 256>>>(ei, as1, ad1, emax1, E, N);
        edge_exp_kernel<4><<<(total + 255) / 256, 256>>>(ei, as1, ad1, emax1, eexp1, denom1, E, N);
    }
    {
        long long warps = ETOT;   // 1 edge per warp (128 ch / 4 per lane)
        int blocks = (int)((warps * 32 + 255) / 256);
        edge_aggregate_kernel<128, 4><<<blocks, 256>>>(ei, H1, eexp1, denom1, out1, E, N);
    }
    elu_kernel<<<(N * 128 + 255) / 256, 256>>>(out1, N * 128);

    // ---------- Layer 2 (HT=64, HEADS=1) ----------
    gemm_kernel<64><<<(N + 63) / 64, 256>>>(out1, W2, H2, N);
    asad_kernel<64, 1><<<N, 64>>>(H2, as2w, ad2w, as2, ad2);
    init_out_kernel<<<(N * 64 + 255) / 256, 256>>>(out, b2, N * 64, 64);
    init_softmax_kernel<<<(N + 255) / 256, 256>>>(emax2, denom2, N);
    {
        int total = ETOT;
        edge_max_kernel<1><<<(total + 255) / 256, 256>>>(ei, as2, ad2, emax2, E, N);
        edge_exp_kernel<1><<<(total + 255) / 256, 256>>>(ei, as2, ad2, emax2, eexp2, denom2, E, N);
    }
    {
        long long warps = (ETOT + 1) / 2;  // 2 edges per warp (64 ch / 4 per lane)
        int blocks = (int)((warps * 32 + 255) / 256);
        edge_aggregate_kernel<64, 1><<<blocks, 256>>>(ei, H2, eexp2, denom2, out, E, N);
    }
}

// round 4
// speedup vs baseline: 1.6174x; 1.6174x over previous
#include <cuda_runtime.h>
#include <cuda_bf16.h>
#include <math.h>

// ---------------------------------------------------------------------------
// GAT 2-layer pipeline, CSR gather formulation.
// N=50000, E=800000 (+N self loops), F_IN=128, L1: 4 heads x 32 (HT=128),
// L2: 1 head x 64. edge_index dtype detected at runtime (int32 vs int64).
//
// Per layer: GEMM -> as/ad -> (shared CSR) -> fused gather:
//   out[d,:] = act( (sum_e exp(lrelu(as[s]+ad[d])) * h[s,:]) / denom[d] + bias )
// No segment-max (logit magnitudes are small; exp cannot overflow) and the
// softmax division is deferred to the epilogue, so softmax+aggregate is ONE
// pass with zero float atomics.
// ---------------------------------------------------------------------------

#define NMAX     50000
#define EMAX     800000
#define ETOTMAX  (EMAX + NMAX)

// scratch (device globals; no cudaMalloc allowed)
__device__ __align__(16) float g_H1[NMAX * 128];
__device__ __align__(16) float g_as1[NMAX * 4];
__device__ __align__(16) float g_ad1[NMAX * 4];
__device__ __align__(16) float g_out1[NMAX * 128];
__device__ __align__(16) float g_H2[NMAX * 64];
__device__ __align__(16) float g_as2[NMAX];
__device__ __align__(16) float g_ad2[NMAX];
// CSR
__device__ int g_deg[NMAX];
__device__ int g_off[NMAX + 1];
__device__ int g_cursor[NMAX];
__device__ int g_csr_src[ETOTMAX];
__device__ int g_bsum[256];
__device__ int g_is64;

// ---------------------------------------------------------------------------
__global__ void detect_dtype_kernel(const int* __restrict__ ei32)
{
    int all_zero = 1;
    #pragma unroll
    for (int i = 1; i < 64; i += 2)
        if (ei32[i] != 0) all_zero = 0;
    g_is64 = all_zero;
}

__device__ __forceinline__ void edge_sd(const int* __restrict__ ei32,
                                        long long e, int E, int is64,
                                        int& s, int& d)
{
    if (e < E) {
        if (is64) { s = ei32[2 * e]; d = ei32[2 * ((long long)E + e)]; }
        else      { s = ei32[e];     d = ei32[(long long)E + e]; }
    } else {
        s = d = (int)(e - E);
    }
}

// ---------------------------------------------------------------------------
// CSR build
// ---------------------------------------------------------------------------
__global__ void count_kernel(const int* __restrict__ ei, int* __restrict__ deg,
                             int E, int N)
{
    int e = blockIdx.x * blockDim.x + threadIdx.x;
    if (e >= E + N) return;
    int s, d;
    edge_sd(ei, e, E, g_is64, s, d);
    atomicAdd(&deg[d], 1);
}

// exclusive scan of 256 ints per block
__device__ __forceinline__ int block_exscan256(int v, int tid)
{
    int lane = tid & 31, wid = tid >> 5;
    int x = v;
    #pragma unroll
    for (int o = 1; o < 32; o <<= 1) {
        int y = __shfl_up_sync(0xffffffffu, x, o);
        if (lane >= o) x += y;
    }
    __shared__ int ws[8];
    if (lane == 31) ws[wid] = x;
    __syncthreads();
    if (wid == 0) {
        int t = (lane < 8) ? ws[lane] : 0;
        #pragma unroll
        for (int o = 1; o < 8; o <<= 1) {
            int y = __shfl_up_sync(0xffffffffu, t, o);
            if (lane >= o) t += y;
        }
        if (lane < 8) ws[lane] = t;
    }
    __syncthreads();
    int base = wid > 0 ? ws[wid - 1] : 0;
    return x + base;   // inclusive; caller subtracts v for exclusive
}

__global__ void scan_local_kernel(const int* __restrict__ deg, int* __restrict__ off,
                                  int* __restrict__ bsum, int n)
{
    int i = blockIdx.x * 256 + threadIdx.x;
    int v = (i < n) ? deg[i] : 0;
    int incl = block_exscan256(v, threadIdx.x);
    if (i < n) off[i] = incl - v;
    if (threadIdx.x == 255) bsum[blockIdx.x] = incl;
}

__global__ void scan_bsum_kernel(int* __restrict__ bsum, int nb)
{
    int i = threadIdx.x;
    int v = (i < nb) ? bsum[i] : 0;
    int incl = block_exscan256(v, i);
    if (i < nb) bsum[i] = incl - v;
}

__global__ void scan_add_kernel(int* __restrict__ off, const int* __restrict__ bsum,
                                int n, int total)
{
    int i = blockIdx.x * 256 + threadIdx.x;
    if (i < n) off[i] += bsum[blockIdx.x];
    if (i == 0) off[n] = total;
}

__global__ void fill_kernel(const int* __restrict__ ei, int* __restrict__ cursor,
                            int* __restrict__ csr_src, int E, int N)
{
    int e = blockIdx.x * blockDim.x + threadIdx.x;
    if (e >= E + N) return;
    int s, d;
    edge_sd(ei, e, E, g_is64, s, d);
    int pos = atomicAdd(&cursor[d], 1);
    csr_src[pos] = s;
}

// ---------------------------------------------------------------------------
// GEMM: C[N, COLS] = A[N, 128] @ W[128, COLS], fp32 SIMT.
// ---------------------------------------------------------------------------
template <int COLS>
__global__ __launch_bounds__(256) void gemm_kernel(
    const float* __restrict__ A, const float* __restrict__ W,
    float* __restrict__ C, int N)
{
    constexpr int K = 128;
    constexpr int MTILE = 64;
    constexpr int G = COLS / 4;
    constexpr int R = 256 / G;
    constexpr int RT = MTILE / R;

    __shared__ float Xs[MTILE][K];

    const int tid = threadIdx.x;
    const int block_row = blockIdx.x * MTILE;

    #pragma unroll
    for (int i = tid; i < MTILE * (K / 4); i += 256) {
        int r = i / (K / 4);
        int c4 = i % (K / 4);
        int gr = block_row + r;
        float4 v = make_float4(0.f, 0.f, 0.f, 0.f);
        if (gr < N) v = ((const float4*)A)[(size_t)gr * (K / 4) + c4];
        *(float4*)&Xs[r][c4 * 4] = v;
    }
    __syncthreads();

    const int cg = tid % G;
    const int rg = tid / G;

    float acc[RT][4];
    #pragma unroll
    for (int r = 0; r < RT; r++) {
        acc[r][0] = 0.f; acc[r][1] = 0.f; acc[r][2] = 0.f; acc[r][3] = 0.f;
    }

    #pragma unroll 4
    for (int k = 0; k < K; k++) {
        float4 w = ((const float4*)W)[k * G + cg];
        #pragma unroll
        for (int r = 0; r < RT; r++) {
            float a = Xs[rg * RT + r][k];
            acc[r][0] = fmaf(a, w.x, acc[r][0]);
            acc[r][1] = fmaf(a, w.y, acc[r][1]);
            acc[r][2] = fmaf(a, w.z, acc[r][2]);
            acc[r][3] = fmaf(a, w.w, acc[r][3]);
        }
    }

    #pragma unroll
    for (int r = 0; r < RT; r++) {
        int gr = block_row + rg * RT + r;
        if (gr < N)
            ((float4*)C)[(size_t)gr * G + cg] =
                make_float4(acc[r][0], acc[r][1], acc[r][2], acc[r][3]);
    }
}

// ---------------------------------------------------------------------------
// per-node attention coefficients
// ---------------------------------------------------------------------------
template <int HT, int HEADS>
__global__ void asad_kernel(const float* __restrict__ H,
                            const float* __restrict__ att_s,
                            const float* __restrict__ att_d,
                            float* __restrict__ as_out,
                            float* __restrict__ ad_out)
{
    constexpr int C = HT / HEADS;
    constexpr int NWARPS = HT / 32;
    constexpr int WPH = C / 32;

    const int n = blockIdx.x;
    const int t = threadIdx.x;

    float h = H[(size_t)n * HT + t];
    float ps = h * att_s[t];
    float pd = h * att_d[t];

    #pragma unroll
    for (int off = 16; off > 0; off >>= 1) {
        ps += __shfl_xor_sync(0xffffffffu, ps, off);
        pd += __shfl_xor_sync(0xffffffffu, pd, off);
    }

    __shared__ float ss[NWARPS], sd[NWARPS];
    if ((t & 31) == 0) { ss[t >> 5] = ps; sd[t >> 5] = pd; }
    __syncthreads();

    if (t < HEADS) {
        float s = 0.f, d = 0.f;
        #pragma unroll
        for (int w = 0; w < WPH; w++) {
            s += ss[t * WPH + w];
            d += sd[t * WPH + w];
        }
        as_out[n * HEADS + t] = s;
        ad_out[n * HEADS + t] = d;
    }
}

// ---------------------------------------------------------------------------
// Fused softmax + aggregation, gather form. One warp per dst node.
// Layer 1: HT=128, 4 heads; lane owns float4 channels [4*lane, 4*lane+4).
// Epilogue: /denom + bias, ELU.
// ---------------------------------------------------------------------------
__global__ __launch_bounds__(256) void gather128_kernel(
    const int* __restrict__ off, const int* __restrict__ csr_src,
    const float* __restrict__ H,
    const float* __restrict__ as_, const float* __restrict__ ad_,
    const float* __restrict__ bias,
    float* __restrict__ out, int N)
{
    int w = (blockIdx.x * blockDim.x + threadIdx.x) >> 5;
    int lane = threadIdx.x & 31;
    if (w >= N) return;
    int n = w;
    int h = lane >> 3;                      // head (4 heads x 8 lanes)

    float ad_v = ad_[n * 4 + h];
    int beg = off[n], end = off[n + 1];

    float4 acc = make_float4(0.f, 0.f, 0.f, 0.f);
    float dsum = 0.f;

    int k = beg;
    int s_next = (k < end) ? csr_src[k] : 0;
    for (; k < end; ) {
        int s = s_next;
        int kn = k + 1;
        if (kn < end) s_next = csr_src[kn];
        float v = as_[s * 4 + h] + ad_v;
        v = v > 0.f ? v : 0.2f * v;
        float ex = __expf(v);
        dsum += ex;
        float4 hv = ((const float4*)H)[(size_t)s * 32 + lane];
        acc.x = fmaf(ex, hv.x, acc.x);
        acc.y = fmaf(ex, hv.y, acc.y);
        acc.z = fmaf(ex, hv.z, acc.z);
        acc.w = fmaf(ex, hv.w, acc.w);
        k = kn;
    }

    float inv = 1.0f / dsum;               // every dst has >=1 edge (self loop)
    float4 b = ((const float4*)bias)[lane];
    float4 r;
    r.x = acc.x * inv + b.x;
    r.y = acc.y * inv + b.y;
    r.z = acc.z * inv + b.z;
    r.w = acc.w * inv + b.w;
    // ELU
    r.x = r.x > 0.f ? r.x : expm1f(r.x);
    r.y = r.y > 0.f ? r.y : expm1f(r.y);
    r.z = r.z > 0.f ? r.z : expm1f(r.z);
    r.w = r.w > 0.f ? r.w : expm1f(r.w);
    ((float4*)out)[(size_t)n * 32 + lane] = r;
}

// Layer 2: HT=64, 1 head; lane owns float2 channels. Epilogue: /denom + bias.
__global__ __launch_bounds__(256) void gather64_kernel(
    const int* __restrict__ off, const int* __restrict__ csr_src,
    const float* __restrict__ H,
    const float* __restrict__ as_, const float* __restrict__ ad_,
    const float* __restrict__ bias,
    float* __restrict__ out, int N)
{
    int w = (blockIdx.x * blockDim.x + threadIdx.x) >> 5;
    int lane = threadIdx.x & 31;
    if (w >= N) return;
    int n = w;

    float ad_v = ad_[n];
    int beg = off[n], end = off[n + 1];

    float2 acc = make_float2(0.f, 0.f);
    float dsum = 0.f;

    int k = beg;
    int s_next = (k < end) ? csr_src[k] : 0;
    for (; k < end; ) {
        int s = s_next;
        int kn = k + 1;
        if (kn < end) s_next = csr_src[kn];
        float v = as_[s] + ad_v;
        v = v > 0.f ? v : 0.2f * v;
        float ex = __expf(v);
        dsum += ex;
        float2 hv = ((const float2*)H)[(size_t)s * 32 + lane];
        acc.x = fmaf(ex, hv.x, acc.x);
        acc.y = fmaf(ex, hv.y, acc.y);
        k = kn;
    }

    float inv = 1.0f / dsum;
    float2 b = ((const float2*)bias)[lane];
    float2 r;
    r.x = acc.x * inv + b.x;
    r.y = acc.y * inv + b.y;
    ((float2*)out)[(size_t)n * 32 + lane] = r;
}

// ---------------------------------------------------------------------------
// launch
// ---------------------------------------------------------------------------
extern "C" void kernel_launch(void* const* d_in, const int* in_sizes, int n_in,
                              void* d_out, int out_size)
{
    const float* x    = (const float*)d_in[0];
    const int*   ei   = (const int*)d_in[1];
    const float* W1   = (const float*)d_in[2];
    const float* as1w = (const float*)d_in[3];
    const float* ad1w = (const float*)d_in[4];
    const float* b1   = (const float*)d_in[5];
    const float* W2   = (const float*)d_in[6];
    const float* as2w = (const float*)d_in[7];
    const float* ad2w = (const float*)d_in[8];
    const float* b2   = (const float*)d_in[9];
    float* out = (float*)d_out;

    const int N = in_sizes[0] / 128;   // 50000
    const int E = in_sizes[1] / 2;     // 800000
    const int ETOT = E + N;

    float *H1, *as1, *ad1, *out1, *H2, *as2, *ad2;
    int *deg, *off, *cursor, *csr_src, *bsum;
    cudaGetSymbolAddress((void**)&H1, g_H1);
    cudaGetSymbolAddress((void**)&as1, g_as1);
    cudaGetSymbolAddress((void**)&ad1, g_ad1);
    cudaGetSymbolAddress((void**)&out1, g_out1);
    cudaGetSymbolAddress((void**)&H2, g_H2);
    cudaGetSymbolAddress((void**)&as2, g_as2);
    cudaGetSymbolAddress((void**)&ad2, g_ad2);
    cudaGetSymbolAddress((void**)&deg, g_deg);
    cudaGetSymbolAddress((void**)&off, g_off);
    cudaGetSymbolAddress((void**)&cursor, g_cursor);
    cudaGetSymbolAddress((void**)&csr_src, g_csr_src);
    cudaGetSymbolAddress((void**)&bsum, g_bsum);

    detect_dtype_kernel<<<1, 1>>>(ei);

    // ---------- CSR build (shared by both layers) ----------
    cudaMemsetAsync(deg, 0, N * sizeof(int));
    count_kernel<<<(ETOT + 255) / 256, 256>>>(ei, deg, E, N);
    int nblk = (N + 255) / 256;                         // 196
    scan_local_kernel<<<nblk, 256>>>(deg, off, bsum, N);
    scan_bsum_kernel<<<1, 256>>>(bsum, nblk);
    scan_add_kernel<<<nblk, 256>>>(off, bsum, N, ETOT);
    cudaMemcpyAsync(cursor, off, N * sizeof(int), cudaMemcpyDeviceToDevice);
    fill_kernel<<<(ETOT + 255) / 256, 256>>>(ei, cursor, csr_src, E, N);

    // ---------- Layer 1 (HT=128, 4 heads) ----------
    gemm_kernel<128><<<(N + 63) / 64, 256>>>(x, W1, H1, N);
    asad_kernel<128, 4><<<N, 128>>>(H1, as1w, ad1w, as1, ad1);
    gather128_kernel<<<(N + 7) / 8, 256>>>(off, csr_src, H1, as1, ad1, b1, out1, N);

    // ---------- Layer 2 (HT=64, 1 head) ----------
    gemm_kernel<64><<<(N + 63) / 64, 256>>>(out1, W2, H2, N);
    asad_kernel<64, 1><<<N, 64>>>(H2, as2w, ad2w, as2, ad2);
    gather64_kernel<<<(N + 7) / 8, 256>>>(off, csr_src, H2, as2, ad2, b2, out, N);
}

// round 5
// speedup vs baseline: 2.0246x; 1.2517x over previous
#include <cuda_runtime.h>
#include <cuda_bf16.h>
#include <math.h>

// ---------------------------------------------------------------------------
// GAT 2-layer pipeline, CSR gather formulation, 4-way unrolled gathers,
// asad fused into GEMM epilogue.
// N=50000, E=800000 (+N self loops), F_IN=128, L1: 4 heads x 32 (HT=128),
// L2: 1 head x 64. edge_index dtype detected at runtime (int32 vs int64).
// ---------------------------------------------------------------------------

#define NMAX     50000
#define EMAX     800000
#define ETOTMAX  (EMAX + NMAX)

__device__ __align__(16) float g_H1[NMAX * 128];
__device__ __align__(16) float g_as1[NMAX * 4];
__device__ __align__(16) float g_ad1[NMAX * 4];
__device__ __align__(16) float g_out1[NMAX * 128];
__device__ __align__(16) float g_H2[NMAX * 64];
__device__ __align__(16) float g_as2[NMAX];
__device__ __align__(16) float g_ad2[NMAX];
__device__ int g_deg[NMAX];
__device__ int g_off[NMAX + 1];
__device__ int g_cursor[NMAX];
__device__ int g_csr_src[ETOTMAX];
__device__ int g_bsum[256];
__device__ int g_is64;

// ---------------------------------------------------------------------------
__global__ void detect_dtype_kernel(const int* __restrict__ ei32)
{
    int all_zero = 1;
    #pragma unroll
    for (int i = 1; i < 64; i += 2)
        if (ei32[i] != 0) all_zero = 0;
    g_is64 = all_zero;
}

__device__ __forceinline__ void edge_sd(const int* __restrict__ ei32,
                                        long long e, int E, int is64,
                                        int& s, int& d)
{
    if (e < E) {
        if (is64) { s = ei32[2 * e]; d = ei32[2 * ((long long)E + e)]; }
        else      { s = ei32[e];     d = ei32[(long long)E + e]; }
    } else {
        s = d = (int)(e - E);
    }
}

// ---------------------------------------------------------------------------
// CSR build
// ---------------------------------------------------------------------------
__global__ void count_kernel(const int* __restrict__ ei, int* __restrict__ deg,
                             int E, int N)
{
    int e = blockIdx.x * blockDim.x + threadIdx.x;
    if (e >= E + N) return;
    int s, d;
    edge_sd(ei, e, E, g_is64, s, d);
    atomicAdd(&deg[d], 1);
}

__device__ __forceinline__ int block_exscan256(int v, int tid)
{
    int lane = tid & 31, wid = tid >> 5;
    int x = v;
    #pragma unroll
    for (int o = 1; o < 32; o <<= 1) {
        int y = __shfl_up_sync(0xffffffffu, x, o);
        if (lane >= o) x += y;
    }
    __shared__ int ws[8];
    if (lane == 31) ws[wid] = x;
    __syncthreads();
    if (wid == 0) {
        int t = (lane < 8) ? ws[lane] : 0;
        #pragma unroll
        for (int o = 1; o < 8; o <<= 1) {
            int y = __shfl_up_sync(0xffffffffu, t, o);
            if (lane >= o) t += y;
        }
        if (lane < 8) ws[lane] = t;
    }
    __syncthreads();
    int base = wid > 0 ? ws[wid - 1] : 0;
    return x + base;   // inclusive
}

__global__ void scan_local_kernel(const int* __restrict__ deg, int* __restrict__ off,
                                  int* __restrict__ bsum, int n)
{
    int i = blockIdx.x * 256 + threadIdx.x;
    int v = (i < n) ? deg[i] : 0;
    int incl = block_exscan256(v, threadIdx.x);
    if (i < n) off[i] = incl - v;
    if (threadIdx.x == 255) bsum[blockIdx.x] = incl;
}

__global__ void scan_bsum_kernel(int* __restrict__ bsum, int nb)
{
    int i = threadIdx.x;
    int v = (i < nb) ? bsum[i] : 0;
    int incl = block_exscan256(v, i);
    if (i < nb) bsum[i] = incl - v;
}

__global__ void scan_add_kernel(int* __restrict__ off, const int* __restrict__ bsum,
                                int n, int total)
{
    int i = blockIdx.x * 256 + threadIdx.x;
    if (i < n) off[i] += bsum[blockIdx.x];
    if (i == 0) off[n] = total;
}

__global__ void fill_kernel(const int* __restrict__ ei, int* __restrict__ cursor,
                            int* __restrict__ csr_src, int E, int N)
{
    int e = blockIdx.x * blockDim.x + threadIdx.x;
    if (e >= E + N) return;
    int s, d;
    edge_sd(ei, e, E, g_is64, s, d);
    int pos = atomicAdd(&cursor[d], 1);
    csr_src[pos] = s;
}

// ---------------------------------------------------------------------------
// GEMM + fused asad epilogue.
// C[N, COLS] = A[N, 128] @ W[128, COLS];
// as[n,h] = sum_c C[n,h,c]*att_s[h,c], ad likewise.
// A full output row lives in G consecutive lanes of one warp -> shfl reduce.
// ---------------------------------------------------------------------------
template <int COLS, int HEADS>
__global__ __launch_bounds__(256) void gemm_asad_kernel(
    const float* __restrict__ A, const float* __restrict__ W,
    const float* __restrict__ att_s, const float* __restrict__ att_d,
    float* __restrict__ C, float* __restrict__ as_out, float* __restrict__ ad_out,
    int N)
{
    constexpr int K = 128;
    constexpr int MTILE = 64;
    constexpr int G = COLS / 4;       // lanes per row
    constexpr int R = 256 / G;
    constexpr int RT = MTILE / R;
    constexpr int HID = COLS / HEADS;
    constexpr int RW = HID / 4;       // lanes per head group

    __shared__ float Xs[MTILE][K];

    const int tid = threadIdx.x;
    const int block_row = blockIdx.x * MTILE;

    #pragma unroll
    for (int i = tid; i < MTILE * (K / 4); i += 256) {
        int r = i / (K / 4);
        int c4 = i % (K / 4);
        int gr = block_row + r;
        float4 v = make_float4(0.f, 0.f, 0.f, 0.f);
        if (gr < N) v = ((const float4*)A)[(size_t)gr * (K / 4) + c4];
        *(float4*)&Xs[r][c4 * 4] = v;
    }
    __syncthreads();

    const int cg = tid % G;
    const int rg = tid / G;

    float acc[RT][4];
    #pragma unroll
    for (int r = 0; r < RT; r++) {
        acc[r][0] = 0.f; acc[r][1] = 0.f; acc[r][2] = 0.f; acc[r][3] = 0.f;
    }

    #pragma unroll 4
    for (int k = 0; k < K; k++) {
        float4 w = ((const float4*)W)[k * G + cg];
        #pragma unroll
        for (int r = 0; r < RT; r++) {
            float a = Xs[rg * RT + r][k];
            acc[r][0] = fmaf(a, w.x, acc[r][0]);
            acc[r][1] = fmaf(a, w.y, acc[r][1]);
            acc[r][2] = fmaf(a, w.z, acc[r][2]);
            acc[r][3] = fmaf(a, w.w, acc[r][3]);
        }
    }

    const float4 ws = ((const float4*)att_s)[cg];
    const float4 wd = ((const float4*)att_d)[cg];

    #pragma unroll
    for (int r = 0; r < RT; r++) {
        int gr = block_row + rg * RT + r;
        if (gr < N)
            ((float4*)C)[(size_t)gr * G + cg] =
                make_float4(acc[r][0], acc[r][1], acc[r][2], acc[r][3]);

        float ps = acc[r][0] * ws.x + acc[r][1] * ws.y + acc[r][2] * ws.z + acc[r][3] * ws.w;
        float pd = acc[r][0] * wd.x + acc[r][1] * wd.y + acc[r][2] * wd.z + acc[r][3] * wd.w;
        #pragma unroll
        for (int o = RW / 2; o > 0; o >>= 1) {
            ps += __shfl_xor_sync(0xffffffffu, ps, o);
            pd += __shfl_xor_sync(0xffffffffu, pd, o);
        }
        if ((cg % RW) == 0 && gr < N) {
            int head = cg / RW;
            as_out[gr * HEADS + head] = ps;
            ad_out[gr * HEADS + head] = pd;
        }
    }
}

// ---------------------------------------------------------------------------
// Fused softmax + aggregation, gather form, 4-way unrolled for MLP.
// One warp per dst node.
// ---------------------------------------------------------------------------
__global__ __launch_bounds__(256) void gather128_kernel(
    const int* __restrict__ off, const int* __restrict__ csr_src,
    const float* __restrict__ H,
    const float* __restrict__ as_, const float* __restrict__ ad_,
    const float* __restrict__ bias,
    float* __restrict__ out, int N)
{
    int w = (blockIdx.x * blockDim.x + threadIdx.x) >> 5;
    int lane = threadIdx.x & 31;
    if (w >= N) return;
    int n = w;
    int h = lane >> 3;                      // head (4 heads x 8 lanes)

    const float ad_v = ad_[n * 4 + h];
    int beg = off[n], end = off[n + 1];
    const float4* __restrict__ H4 = (const float4*)H;

    float4 acc = make_float4(0.f, 0.f, 0.f, 0.f);
    float dsum = 0.f;

    int k = beg;
    for (; k + 4 <= end; k += 4) {
        int s0 = csr_src[k], s1 = csr_src[k + 1], s2 = csr_src[k + 2], s3 = csr_src[k + 3];
        float a0 = as_[s0 * 4 + h];
        float a1 = as_[s1 * 4 + h];
        float a2 = as_[s2 * 4 + h];
        float a3 = as_[s3 * 4 + h];
        float4 h0 = H4[(size_t)s0 * 32 + lane];
        float4 h1 = H4[(size_t)s1 * 32 + lane];
        float4 h2 = H4[(size_t)s2 * 32 + lane];
        float4 h3 = H4[(size_t)s3 * 32 + lane];
        float v0 = a0 + ad_v; v0 = v0 > 0.f ? v0 : 0.2f * v0; float e0 = __expf(v0);
        float v1 = a1 + ad_v; v1 = v1 > 0.f ? v1 : 0.2f * v1; float e1 = __expf(v1);
        float v2 = a2 + ad_v; v2 = v2 > 0.f ? v2 : 0.2f * v2; float e2 = __expf(v2);
        float v3 = a3 + ad_v; v3 = v3 > 0.f ? v3 : 0.2f * v3; float e3 = __expf(v3);
        dsum += (e0 + e1) + (e2 + e3);
        acc.x = fmaf(e0, h0.x, acc.x); acc.y = fmaf(e0, h0.y, acc.y);
        acc.z = fmaf(e0, h0.z, acc.z); acc.w = fmaf(e0, h0.w, acc.w);
        acc.x = fmaf(e1, h1.x, acc.x); acc.y = fmaf(e1, h1.y, acc.y);
        acc.z = fmaf(e1, h1.z, acc.z); acc.w = fmaf(e1, h1.w, acc.w);
        acc.x = fmaf(e2, h2.x, acc.x); acc.y = fmaf(e2, h2.y, acc.y);
        acc.z = fmaf(e2, h2.z, acc.z); acc.w = fmaf(e2, h2.w, acc.w);
        acc.x = fmaf(e3, h3.x, acc.x); acc.y = fmaf(e3, h3.y, acc.y);
        acc.z = fmaf(e3, h3.z, acc.z); acc.w = fmaf(e3, h3.w, acc.w);
    }
    for (; k < end; k++) {
        int s = csr_src[k];
        float v = as_[s * 4 + h] + ad_v;
        v = v > 0.f ? v : 0.2f * v;
        float ex = __expf(v);
        dsum += ex;
        float4 hv = H4[(size_t)s * 32 + lane];
        acc.x = fmaf(ex, hv.x, acc.x);
        acc.y = fmaf(ex, hv.y, acc.y);
        acc.z = fmaf(ex, hv.z, acc.z);
        acc.w = fmaf(ex, hv.w, acc.w);
    }

    float inv = 1.0f / dsum;
    float4 b = ((const float4*)bias)[lane];
    float4 r;
    r.x = acc.x * inv + b.x;
    r.y = acc.y * inv + b.y;
    r.z = acc.z * inv + b.z;
    r.w = acc.w * inv + b.w;
    r.x = r.x > 0.f ? r.x : expm1f(r.x);
    r.y = r.y > 0.f ? r.y : expm1f(r.y);
    r.z = r.z > 0.f ? r.z : expm1f(r.z);
    r.w = r.w > 0.f ? r.w : expm1f(r.w);
    ((float4*)out)[(size_t)n * 32 + lane] = r;
}

__global__ __launch_bounds__(256) void gather64_kernel(
    const int* __restrict__ off, const int* __restrict__ csr_src,
    const float* __restrict__ H,
    const float* __restrict__ as_, const float* __restrict__ ad_,
    const float* __restrict__ bias,
    float* __restrict__ out, int N)
{
    int w = (blockIdx.x * blockDim.x + threadIdx.x) >> 5;
    int lane = threadIdx.x & 31;
    if (w >= N) return;
    int n = w;

    const float ad_v = ad_[n];
    int beg = off[n], end = off[n + 1];
    const float2* __restrict__ H2 = (const float2*)H;

    float2 acc = make_float2(0.f, 0.f);
    float dsum = 0.f;

    int k = beg;
    for (; k + 4 <= end; k += 4) {
        int s0 = csr_src[k], s1 = csr_src[k + 1], s2 = csr_src[k + 2], s3 = csr_src[k + 3];
        float a0 = as_[s0], a1 = as_[s1], a2 = as_[s2], a3 = as_[s3];
        float2 h0 = H2[(size_t)s0 * 32 + lane];
        float2 h1 = H2[(size_t)s1 * 32 + lane];
        float2 h2 = H2[(size_t)s2 * 32 + lane];
        float2 h3 = H2[(size_t)s3 * 32 + lane];
        float v0 = a0 + ad_v; v0 = v0 > 0.f ? v0 : 0.2f * v0; float e0 = __expf(v0);
        float v1 = a1 + ad_v; v1 = v1 > 0.f ? v1 : 0.2f * v1; float e1 = __expf(v1);
        float v2 = a2 + ad_v; v2 = v2 > 0.f ? v2 : 0.2f * v2; float e2 = __expf(v2);
        float v3 = a3 + ad_v; v3 = v3 > 0.f ? v3 : 0.2f * v3; float e3 = __expf(v3);
        dsum += (e0 + e1) + (e2 + e3);
        acc.x = fmaf(e0, h0.x, acc.x); acc.y = fmaf(e0, h0.y, acc.y);
        acc.x = fmaf(e1, h1.x, acc.x); acc.y = fmaf(e1, h1.y, acc.y);
        acc.x = fmaf(e2, h2.x, acc.x); acc.y = fmaf(e2, h2.y, acc.y);
        acc.x = fmaf(e3, h3.x, acc.x); acc.y = fmaf(e3, h3.y, acc.y);
    }
    for (; k < end; k++) {
        int s = csr_src[k];
        float v = as_[s] + ad_v;
        v = v > 0.f ? v : 0.2f * v;
        float ex = __expf(v);
        dsum += ex;
        float2 hv = H2[(size_t)s * 32 + lane];
        acc.x = fmaf(ex, hv.x, acc.x);
        acc.y = fmaf(ex, hv.y, acc.y);
    }

    float inv = 1.0f / dsum;
    float2 b = ((const float2*)bias)[lane];
    float2 r;
    r.x = acc.x * inv + b.x;
    r.y = acc.y * inv + b.y;
    ((float2*)out)[(size_t)n * 32 + lane] = r;
}

// ---------------------------------------------------------------------------
// launch
// ---------------------------------------------------------------------------
extern "C" void kernel_launch(void* const* d_in, const int* in_sizes, int n_in,
                              void* d_out, int out_size)
{
    const float* x    = (const float*)d_in[0];
    const int*   ei   = (const int*)d_in[1];
    const float* W1   = (const float*)d_in[2];
    const float* as1w = (const float*)d_in[3];
    const float* ad1w = (const float*)d_in[4];
    const float* b1   = (const float*)d_in[5];
    const float* W2   = (const float*)d_in[6];
    const float* as2w = (const float*)d_in[7];
    const float* ad2w = (const float*)d_in[8];
    const float* b2   = (const float*)d_in[9];
    float* out = (float*)d_out;

    const int N = in_sizes[0] / 128;   // 50000
    const int E = in_sizes[1] / 2;     // 800000
    const int ETOT = E + N;

    float *H1, *as1, *ad1, *out1, *H2, *as2, *ad2;
    int *deg, *off, *cursor, *csr_src, *bsum;
    cudaGetSymbolAddress((void**)&H1, g_H1);
    cudaGetSymbolAddress((void**)&as1, g_as1);
    cudaGetSymbolAddress((void**)&ad1, g_ad1);
    cudaGetSymbolAddress((void**)&out1, g_out1);
    cudaGetSymbolAddress((void**)&H2, g_H2);
    cudaGetSymbolAddress((void**)&as2, g_as2);
    cudaGetSymbolAddress((void**)&ad2, g_ad2);
    cudaGetSymbolAddress((void**)&deg, g_deg);
    cudaGetSymbolAddress((void**)&off, g_off);
    cudaGetSymbolAddress((void**)&cursor, g_cursor);
    cudaGetSymbolAddress((void**)&csr_src, g_csr_src);
    cudaGetSymbolAddress((void**)&bsum, g_bsum);

    detect_dtype_kernel<<<1, 1>>>(ei);

    // ---------- CSR build (shared by both layers) ----------
    cudaMemsetAsync(deg, 0, N * sizeof(int));
    count_kernel<<<(ETOT + 255) / 256, 256>>>(ei, deg, E, N);
    int nblk = (N + 255) / 256;
    scan_local_kernel<<<nblk, 256>>>(deg, off, bsum, N);
    scan_bsum_kernel<<<1, 256>>>(bsum, nblk);
    scan_add_kernel<<<nblk, 256>>>(off, bsum, N, ETOT);
    cudaMemcpyAsync(cursor, off, N * sizeof(int), cudaMemcpyDeviceToDevice);
    fill_kernel<<<(ETOT + 255) / 256, 256>>>(ei, cursor, csr_src, E, N);

    // ---------- Layer 1 (HT=128, 4 heads) ----------
    gemm_asad_kernel<128, 4><<<(N + 63) / 64, 256>>>(x, W1, as1w, ad1w, H1, as1, ad1, N);
    gather128_kernel<<<(N + 7) / 8, 256>>>(off, csr_src, H1, as1, ad1, b1, out1, N);

    // ---------- Layer 2 (HT=64, 1 head) ----------
    gemm_asad_kernel<64, 1><<<(N + 63) / 64, 256>>>(out1, W2, as2w, ad2w, H2, as2, ad2, N);
    gather64_kernel<<<(N + 7) / 8, 256>>>(off, csr_src, H2, as2, ad2, b2, out, N);
}